// round 15
// baseline (speedup 1.0000x reference)
#include <cuda_runtime.h>
#include <cuda_fp16.h>
#include <cstdint>
#include <cstddef>

#define BATCH 8
#define CDIM  256
#define NPIX  4096
#define O1    1536
#define HIDD  512
#define NHEAD 8
#define DHEAD 64

typedef unsigned int u32;

// ---------------- scratch (device globals; no allocation allowed) ----------
__device__ u32    g_qu[BATCH * NHEAD * 32 * NPIX];   // q packed pair-rows
__device__ __half g_kh[BATCH * HIDD * NPIX];         // k half [bh][64][n]
__device__ __half g_vh[BATCH * HIDD * NPIX];         // v half [bh][64][n]
__device__ u32    g_o2u[BATCH * 256 * NPIX];         // out2 packed pair-rows
__device__ float  g_kv[BATCH * NHEAD * DHEAD * DHEAD];
__device__ float  g_ksum[BATCH * NHEAD * DHEAD];
__device__ u32    g_wqh[O1 * (CDIM / 2)];            // Wqkv fp16, col pairs
__device__ u32    g_woh[CDIM * (HIDD / 2)];          // Wout fp16, permuted pairs
__device__ u32    g_xh[BATCH * (CDIM / 2) * NPIX];   // x fp16, row pairs

// ---------------- helpers ---------------------------------------------------
__device__ __forceinline__ u32 h2(float lo, float hi) {
    __half2 t = __floats2half2_rn(lo, hi);
    return *reinterpret_cast<u32*>(&t);
}
__device__ __forceinline__ float elu1f(float x) {
    return x > 0.0f ? x + 1.0f : expf(x);
}
__device__ __forceinline__ void mma_f16(float c[4], const u32 a[4], const u32 b[2]) {
    asm volatile(
        "mma.sync.aligned.m16n8k16.row.col.f32.f16.f16.f32 "
        "{%0,%1,%2,%3}, {%4,%5,%6,%7}, {%8,%9}, {%0,%1,%2,%3};"
        : "+f"(c[0]), "+f"(c[1]), "+f"(c[2]), "+f"(c[3])
        : "r"(a[0]), "r"(a[1]), "r"(a[2]), "r"(a[3]), "r"(b[0]), "r"(b[1]));
}
__device__ __forceinline__ void ldsm_x4(u32& r0, u32& r1, u32& r2, u32& r3, u32 addr) {
    asm volatile("ldmatrix.sync.aligned.m8n8.x4.shared.b16 {%0,%1,%2,%3}, [%4];"
                 : "=r"(r0), "=r"(r1), "=r"(r2), "=r"(r3) : "r"(addr));
}
__device__ __forceinline__ void ldsm_x2(u32& r0, u32& r1, u32 addr) {
    asm volatile("ldmatrix.sync.aligned.m8n8.x2.shared.b16 {%0,%1}, [%2];"
                 : "=r"(r0), "=r"(r1) : "r"(addr));
}
__device__ __forceinline__ void cp_async16(u32 dst, const void* src) {
    asm volatile("cp.async.cg.shared.global [%0], [%1], 16;" :: "r"(dst), "l"(src));
}
__device__ __forceinline__ void cp_commit() {
    asm volatile("cp.async.commit_group;");
}
template <int N> __device__ __forceinline__ void cp_wait() {
    asm volatile("cp.async.wait_group %0;" :: "n"(N));
}
__device__ __forceinline__ u32 smem_addr_of(const void* p) {
    u32 a;
    asm("{ .reg .u64 t; cvta.to.shared.u64 t, %1; cvt.u32.u64 %0, t; }"
        : "=r"(a) : "l"(p));
    return a;
}

// lane-derived ldmatrix offsets (A non-trans pattern)
struct LdsmIdx { int rowoff; int coloff; };
__device__ __forceinline__ LdsmIdx ldsm_idx(int lane) {
    LdsmIdx s;
    s.rowoff = (lane & 7) + ((lane >> 3) & 1) * 8;
    s.coloff = ((lane >> 4) & 1) * 4;
    return s;
}

// ===================== big-GEMM fp16 machinery (round-11 winner) ============
#define A_STRIDE 36
#define B_STRIDE 136
#define A_ELEMS (128 * A_STRIDE)
#define B_ELEMS (32 * B_STRIDE)
#define BUF_ELEMS (A_ELEMS + B_ELEMS)
#define BUF_BYTES (BUF_ELEMS * 4)
#define SMEM_BYTES (3 * BUF_BYTES)          // 107520

struct Frag { float c[2][8][4]; };

__device__ __forceinline__ void stage_cp(
    u32 sbase, const u32* __restrict__ A, int lda,
    const u32* __restrict__ B, int ldb, int o0, int n0, int ku0, int tid)
{
    const u32 abase = sbase;
    const u32 bbase = sbase + A_ELEMS * 4;
#pragma unroll
    for (int i = 0; i < 4; ++i) {
        const int fi = tid + i * 256;
        const int row = fi >> 3, c4 = (fi & 7) * 4;
        cp_async16(abase + (u32)(row * A_STRIDE + c4) * 4,
                   &A[(size_t)(o0 + row) * lda + ku0 + c4]);
    }
#pragma unroll
    for (int i = 0; i < 4; ++i) {
        const int fi = tid + i * 256;
        const int row = fi >> 5, c4 = (fi & 31) * 4;
        cp_async16(bbase + (u32)(row * B_STRIDE + c4) * 4,
                   &B[(size_t)(ku0 + row) * ldb + n0 + c4]);
    }
    cp_commit();
}

__device__ __forceinline__ void chunk_mma(
    Frag& fr, const u32* sm_u, u32 abase_u32,
    int warp_m, int warp_n, int lq, int kq, const LdsmIdx& si)
{
    const u32* Bs = sm_u + A_ELEMS;
#pragma unroll
    for (int ks = 0; ks < 4; ++ks) {
        const int kb = ks * 8 + kq;
        u32 a[2][4];
#pragma unroll
        for (int mt = 0; mt < 2; ++mt) {
            const int row = warp_m + mt * 16 + si.rowoff;
            ldsm_x4(a[mt][0], a[mt][1], a[mt][2], a[mt][3],
                    abase_u32 + (u32)(row * A_STRIDE + ks * 8 + si.coloff) * 4);
        }
        u32 bfr[8][2];
#pragma unroll
        for (int nt = 0; nt < 8; ++nt) {
            const int n = warp_n + nt * 8 + lq;
            bfr[nt][0] = Bs[kb * B_STRIDE + n];
            bfr[nt][1] = Bs[(kb + 4) * B_STRIDE + n];
        }
#pragma unroll
        for (int mt = 0; mt < 2; ++mt)
#pragma unroll
            for (int nt = 0; nt < 8; ++nt)
                mma_f16(fr.c[mt][nt], a[mt], bfr[nt]);
    }
}

__device__ __forceinline__ void gemm_mainloop(
    Frag& fr, const u32* __restrict__ A, int lda,
    const u32* __restrict__ B, int ldb,
    int o0, int n0, int NC, u32* sm_u)
{
    const int tid = threadIdx.x;
    const int wid = tid >> 5, lane = tid & 31;
    const int warp_m = (wid & 3) * 32;
    const int warp_n = (wid >> 2) * 64;
    const int lq = lane >> 2, kq = lane & 3;
    const LdsmIdx si = ldsm_idx(lane);

    const u32 sbase = smem_addr_of(sm_u);

#pragma unroll
    for (int mt = 0; mt < 2; ++mt)
#pragma unroll
        for (int nt = 0; nt < 8; ++nt)
#pragma unroll
            for (int i = 0; i < 4; ++i) fr.c[mt][nt][i] = 0.0f;

    stage_cp(sbase, A, lda, B, ldb, o0, n0, 0, tid);
    stage_cp(sbase + BUF_BYTES, A, lda, B, ldb, o0, n0, 32, tid);

    for (int c = 0; c < NC; ++c) {
        if (c < NC - 1) cp_wait<1>(); else cp_wait<0>();
        __syncthreads();
        if (c + 2 < NC)
            stage_cp(sbase + (u32)((c + 2) % 3) * BUF_BYTES,
                     A, lda, B, ldb, o0, n0, (c + 2) * 32, tid);
        const int cur = c % 3;
        chunk_mma(fr, sm_u + (size_t)cur * BUF_ELEMS,
                  sbase + (u32)cur * BUF_BYTES, warp_m, warp_n, lq, kq, si);
    }
}

// ============================================================================
// Kernel 0: fused preconv — pack x (row pairs) + Wqkv + Wout to fp16.
// ============================================================================
#define NX4  (BATCH * 128 * NPIX / 4)
#define NWQ_U (O1 * (CDIM / 2))
#define NWO_U (CDIM * (HIDD / 2))

__global__ __launch_bounds__(256) void preconv_kernel(
    const float* __restrict__ x,
    const float* __restrict__ wq, const float* __restrict__ wo)
{
    const int i = blockIdx.x * 256 + threadIdx.x;
    if (i < NX4) {
        const int n4 = (i & 1023) * 4;
        const int j  = (i >> 10) & 127;
        const int b  = i >> 17;
        const float* r0 = &x[((size_t)b * CDIM + 2 * j) * NPIX + n4];
        const float* r1 = r0 + NPIX;
        float4 a = *reinterpret_cast<const float4*>(r0);
        float4 c = *reinterpret_cast<const float4*>(r1);
        uint4 w;
        w.x = h2(a.x, c.x); w.y = h2(a.y, c.y);
        w.z = h2(a.z, c.z); w.w = h2(a.w, c.w);
        *reinterpret_cast<uint4*>(&g_xh[(((size_t)b * 128 + j) * NPIX + n4)]) = w;
    } else if (i < NX4 + NWQ_U) {
        const int i2 = i - NX4;
        const int o = i2 >> 7, j = i2 & 127;
        const float* p = &wq[(size_t)o * CDIM + 2 * j];
        g_wqh[i2] = h2(p[0], p[1]);
    } else if (i < NX4 + NWQ_U + NWO_U) {
        const int i2 = i - NX4 - NWQ_U;
        const int o = i2 >> 8, jg = i2 & 255;
        const int h = jg >> 5, r = jg & 31;
        const int p0 = h * 64 + ((r >> 3) << 4) + (r & 7);
        g_woh[i2] = h2(wo[(size_t)o * HIDD + p0], wo[(size_t)o * HIDD + p0 + 8]);
    }
}

// ============================================================================
// Kernel 1: qkv GEMM (fp16). Epilogue: q -> packed pair-rows, k/v -> half.
// ============================================================================
__global__ __launch_bounds__(256, 2) void qkv_mma_kernel(
    const float* __restrict__ cm, const float* __restrict__ csp)
{
    extern __shared__ u32 sm_u[];
    const int b  = blockIdx.z;
    const int o0 = blockIdx.y * 128;
    const int n0 = blockIdx.x * 128;

    Frag fr;
    gemm_mainloop(fr, g_wqh, CDIM / 2, g_xh + (size_t)b * 128 * NPIX, NPIX,
                  o0, n0, 4, sm_u);

    const int tid = threadIdx.x;
    const int wid = tid >> 5, lane = tid & 31;
    const int warp_m = (wid & 3) * 32;
    const int warp_n = (wid >> 2) * 64;
    const int lq = lane >> 2, kq = lane & 3;

    const int sec = o0 >> 9;
    const int obase = o0 & 511;
    const float cs = (sec == 1) ? *csp : 0.0f;
    const float* cmb = cm + (size_t)b * NPIX;

#pragma unroll
    for (int nt = 0; nt < 8; ++nt) {
        const int cg = n0 + warp_n + nt * 8 + kq * 2;
        float m0 = 1.0f, m1 = 1.0f;
        if (sec == 1) {
            m0 = 1.0f + cs * cmb[cg];
            m1 = 1.0f + cs * cmb[cg + 1];
        }
#pragma unroll
        for (int mt = 0; mt < 2; ++mt) {
            const int rl = warp_m + mt * 16 + lq;
            const int grow = obase + rl;
            float v0 = fr.c[mt][nt][0], v1 = fr.c[mt][nt][1];
            float v2 = fr.c[mt][nt][2], v3 = fr.c[mt][nt][3];
            if (sec == 0) {
                v0 = elu1f(v0); v1 = elu1f(v1); v2 = elu1f(v2); v3 = elu1f(v3);
                const int h = grow >> 6, wh = grow & 63;
                const int j = ((wh >> 4) << 3) | (wh & 7);
                const size_t urow = (size_t)(b * NHEAD + h) * 32 + j;
                uint2 w;
                w.x = h2(v0, v2);
                w.y = h2(v1, v3);
                *reinterpret_cast<uint2*>(&g_qu[urow * NPIX + cg]) = w;
            } else {
                __half* dst = (sec == 1) ? g_kh : g_vh;
                if (sec == 1) {
                    v0 = elu1f(v0) * m0; v1 = elu1f(v1) * m1;
                    v2 = elu1f(v2) * m0; v3 = elu1f(v3) * m1;
                }
                *reinterpret_cast<u32*>(
                    &dst[((size_t)b * HIDD + grow) * NPIX + cg]) = h2(v0, v1);
                *reinterpret_cast<u32*>(
                    &dst[((size_t)b * HIDD + grow + 8) * NPIX + cg]) = h2(v2, v3);
            }
        }
    }
}

// ============================================================================
// Kernel 4: y = Wout @ out2 + bout
// ============================================================================
__global__ __launch_bounds__(256, 2) void out_mma_kernel(
    const float* __restrict__ bout, float* __restrict__ y)
{
    extern __shared__ u32 sm_u[];
    const int b  = blockIdx.z;
    const int o0 = blockIdx.y * 128;
    const int n0 = blockIdx.x * 128;

    Frag fr;
    gemm_mainloop(fr, g_woh, HIDD / 2, g_o2u + (size_t)b * 256 * NPIX, NPIX,
                  o0, n0, 8, sm_u);

    const int tid = threadIdx.x;
    const int wid = tid >> 5, lane = tid & 31;
    const int warp_m = (wid & 3) * 32;
    const int warp_n = (wid >> 2) * 64;
    const int lq = lane >> 2, kq = lane & 3;

#pragma unroll
    for (int mt = 0; mt < 2; ++mt) {
        const int rl = warp_m + mt * 16 + lq;
#pragma unroll
        for (int ri = 0; ri < 2; ++ri) {
            const int grow = o0 + rl + ri * 8;
            const float bo = bout[grow];
#pragma unroll
            for (int nt = 0; nt < 8; ++nt) {
                const int cg = n0 + warp_n + nt * 8 + kq * 2;
                float2 w;
                w.x = fr.c[mt][nt][2 * ri + 0] + bo;
                w.y = fr.c[mt][nt][2 * ri + 1] + bo;
                *reinterpret_cast<float2*>(
                    &y[((size_t)b * CDIM + grow) * NPIX + cg]) = w;
            }
        }
    }
}

// ============================================================================
// Kernel 2 (fp16 MMA, fully async): A = k [64 d][np], B = v [80 e][np]
// (v rows 0-63 via cp.async; row 64 = ones, rows 65-79 = 0, static).
// out[d][e<64] -> kv (atomic), out[d][64] -> ksum (atomic).
// Grid (4 splits, 64 bh); 8 chunks of 64 np (128 n), 2 buffers.
// ============================================================================
#define KV_ASTR 68
#define KV_BSTR 68
#define KV_AE (64 * KV_ASTR)
#define KV_BE (80 * KV_BSTR)
#define KV_SMEM_BYTES ((2 * KV_AE + 2 * KV_BE) * 4)   // 78336

__global__ __launch_bounds__(256) void kv_mma_kernel()
{
    extern __shared__ u32 sm_u[];
    u32* As = sm_u;
    u32* Bs = sm_u + 2 * KV_AE;
    const u32 a_sbase = smem_addr_of(As);
    const u32 b_sbase = smem_addr_of(Bs);

    const int bh    = blockIdx.y;
    const int split = blockIdx.x;
    const int tid = threadIdx.x;
    const int wid = tid >> 5, lane = tid & 31;
    const int warp_m = (wid & 3) * 16;
    const int warp_n = (wid >> 2) * 40;
    const int lq = lane >> 2, kq = lane & 3;
    const LdsmIdx si = ldsm_idx(lane);

    const int b_row = (lane & 7) + ((lane >> 4) & 1) * 8;
    const int b_col = ((lane >> 3) & 1) * 4;
    const int l2 = lane & 15;
    const int b2_row = l2 & 7;
    const int b2_col = ((l2 >> 3) & 1) * 4;

    const u32* kbase = reinterpret_cast<const u32*>(g_kh)
                       + (size_t)bh * 64 * 2048 + split * 512;
    const u32* vbase = reinterpret_cast<const u32*>(g_vh)
                       + (size_t)bh * 64 * 2048 + split * 512;

    for (int f = tid; f < 16 * 64 * 2; f += 256) {
        const int buf = f >> 10;
        const int r = 64 + ((f >> 6) & 15), c = f & 63;
        Bs[buf * KV_BE + r * KV_BSTR + c] = (r == 64) ? 0x3C003C00u : 0u;
    }

    auto stage = [&](int cu0, int buf) {
#pragma unroll
        for (int i = 0; i < 4; ++i) {
            const int f = tid + i * 256;
            const int d = f >> 4, c4 = (f & 15) * 4;
            cp_async16(a_sbase + (u32)(buf * KV_AE + d * KV_ASTR + c4) * 4,
                       &kbase[(size_t)d * 2048 + cu0 + c4]);
        }
#pragma unroll
        for (int i = 0; i < 4; ++i) {
            const int f = tid + i * 256;
            const int e = f >> 4, c4 = (f & 15) * 4;
            cp_async16(b_sbase + (u32)(buf * KV_BE + e * KV_BSTR + c4) * 4,
                       &vbase[(size_t)e * 2048 + cu0 + c4]);
        }
        cp_commit();
    };

    float fr[5][4];
#pragma unroll
    for (int nt = 0; nt < 5; ++nt)
#pragma unroll
        for (int i = 0; i < 4; ++i) fr[nt][i] = 0.0f;

    stage(0, 0);
    stage(64, 1);

    for (int c = 0; c < 8; ++c) {
        if (c < 7) cp_wait<1>(); else cp_wait<0>();
        __syncthreads();

        const int cur = c & 1;
        const u32 ab = a_sbase + (u32)(cur * KV_AE) * 4;
        const u32 bb = b_sbase + (u32)(cur * KV_BE) * 4;
#pragma unroll
        for (int ks = 0; ks < 8; ++ks) {
            u32 a[4];
            ldsm_x4(a[0], a[1], a[2], a[3],
                    ab + (u32)((warp_m + si.rowoff) * KV_ASTR + ks * 8 + si.coloff) * 4);
            u32 bfr[5][2];
            ldsm_x4(bfr[0][0], bfr[0][1], bfr[1][0], bfr[1][1],
                    bb + (u32)((warp_n + b_row) * KV_BSTR + ks * 8 + b_col) * 4);
            ldsm_x4(bfr[2][0], bfr[2][1], bfr[3][0], bfr[3][1],
                    bb + (u32)((warp_n + 16 + b_row) * KV_BSTR + ks * 8 + b_col) * 4);
            ldsm_x2(bfr[4][0], bfr[4][1],
                    bb + (u32)((warp_n + 32 + b2_row) * KV_BSTR + ks * 8 + b2_col) * 4);
#pragma unroll
            for (int nt = 0; nt < 5; ++nt)
                mma_f16(fr[nt], a, bfr[nt]);
        }

        if (c < 6) {
            __syncthreads();
            stage((c + 2) * 64, cur);
        }
    }

    float* kvout = g_kv + (size_t)bh * DHEAD * DHEAD;
    float* ksout = g_ksum + (size_t)bh * DHEAD;
#pragma unroll
    for (int nt = 0; nt < 5; ++nt) {
#pragma unroll
        for (int i = 0; i < 4; ++i) {
            const int e = warp_n + nt * 8 + kq * 2 + (i & 1);
            const int d = warp_m + lq + (i >> 1) * 8;
            if (e < 64)       atomicAdd(&kvout[d * DHEAD + e], fr[nt][i]);
            else if (e == 64) atomicAdd(&ksout[d], fr[nt][i]);
        }
    }
}

// ============================================================================
// Kernel 3 (fp16 MMA): A = [kv^T pairs ; ksum row 64 ; 0 pad], B = q packed.
// ============================================================================
#define AT_ASTR 36
#define AT_AE (80 * AT_ASTR)
#define AT_BSTR 264
#define AT_BE (32 * AT_BSTR)
#define AT_SMEM_BYTES ((AT_AE + AT_BE) * 4)

__global__ __launch_bounds__(256, 2) void attn_mma_kernel()
{
    extern __shared__ u32 sm_u[];
    u32* As = sm_u;
    u32* Bs = sm_u + AT_AE;
    const u32 a_sbase = smem_addr_of(As);
    const u32 b_sbase = smem_addr_of(Bs);

    const int bh = blockIdx.y;
    const int n0 = blockIdx.x * 256;
    const int tid = threadIdx.x;
    const int wid = tid >> 5, lane = tid & 31;
    const int warp_n = wid * 32;
    const int lq = lane >> 2, kq = lane & 3;
    const LdsmIdx si = ldsm_idx(lane);

    const u32*   qbase  = g_qu + (size_t)bh * 32 * NPIX;
    const float* kvbase = g_kv + (size_t)bh * DHEAD * DHEAD;

#pragma unroll
    for (int i = 0; i < 8; ++i) {
        const int f = tid + i * 256;
        const int d = f >> 6, c4 = (f & 63) * 4;
        cp_async16(b_sbase + (u32)(d * AT_BSTR + c4) * 4,
                   &qbase[(size_t)d * NPIX + n0 + c4]);
    }
    cp_commit();

    for (int f = tid; f < 15 * AT_ASTR; f += 256) As[65 * AT_ASTR + f] = 0u;
    if (tid < 32) {
        const int j = tid;
        const int p0 = ((j >> 3) << 4) | (j & 7);
        As[64 * AT_ASTR + j] = h2(g_ksum[bh * DHEAD + p0],
                                  g_ksum[bh * DHEAD + p0 + 8]);
    }
    for (int f = tid; f < 64 * 32; f += 256) {
        const int e = f >> 5, j = f & 31;
        const int p0 = ((j >> 3) << 4) | (j & 7);
        As[e * AT_ASTR + j] = h2(kvbase[p0 * DHEAD + e],
                                 kvbase[(p0 + 8) * DHEAD + e]);
    }
    cp_wait<0>();
    __syncthreads();

    float fr[5][4][4];
#pragma unroll
    for (int mt = 0; mt < 5; ++mt)
#pragma unroll
        for (int nt = 0; nt < 4; ++nt)
#pragma unroll
            for (int i = 0; i < 4; ++i) fr[mt][nt][i] = 0.0f;

#pragma unroll
    for (int ks = 0; ks < 4; ++ks) {
        const int kb = ks * 8 + kq;
        u32 a[5][4];
#pragma unroll
        for (int mt = 0; mt < 5; ++mt) {
            const int row = mt * 16 + si.rowoff;
            ldsm_x4(a[mt][0], a[mt][1], a[mt][2], a[mt][3],
                    a_sbase + (u32)(row * AT_ASTR + ks * 8 + si.coloff) * 4);
        }
        u32 bfr[4][2];
#pragma unroll
        for (int nt = 0; nt < 4; ++nt) {
            const int n = warp_n + nt * 8 + lq;
            bfr[nt][0] = Bs[kb * AT_BSTR + n];
            bfr[nt][1] = Bs[(kb + 4) * AT_BSTR + n];
        }
#pragma unroll
        for (int mt = 0; mt < 5; ++mt)
#pragma unroll
            for (int nt = 0; nt < 4; ++nt)
                mma_f16(fr[mt][nt], a[mt], bfr[nt]);
    }

    u32* obase = g_o2u + (size_t)bh * 32 * NPIX;
#pragma unroll
    for (int nt = 0; nt < 4; ++nt) {
        const float den0 = __shfl_sync(0xffffffffu, fr[4][nt][0], kq);
        const float den1 = __shfl_sync(0xffffffffu, fr[4][nt][1], kq);
        const float z0 = 1.0f / (den0 + 1e-6f);
        const float z1 = 1.0f / (den1 + 1e-6f);
        const int cg = n0 + warp_n + nt * 8 + kq * 2;
#pragma unroll
        for (int mt = 0; mt < 4; ++mt) {
            const int j = mt * 8 + lq;
            uint2 w;
            w.x = h2(fr[mt][nt][0] * z0, fr[mt][nt][2] * z0);
            w.y = h2(fr[mt][nt][1] * z1, fr[mt][nt][3] * z1);
            *reinterpret_cast<uint2*>(&obase[(size_t)j * NPIX + cg]) = w;
        }
    }
}

// ============================================================================
extern "C" void kernel_launch(void* const* d_in, const int* in_sizes, int n_in,
                              void* d_out, int out_size)
{
    const float* x    = (const float*)d_in[0];
    const float* cm   = (const float*)d_in[1];
    const float* Wqkv = (const float*)d_in[2];
    const float* Wout = (const float*)d_in[3];
    const float* bout = (const float*)d_in[4];
    const float* cs   = (const float*)d_in[5];
    float* y = (float*)d_out;

    cudaFuncSetAttribute(qkv_mma_kernel,
                         cudaFuncAttributeMaxDynamicSharedMemorySize, SMEM_BYTES);
    cudaFuncSetAttribute(out_mma_kernel,
                         cudaFuncAttributeMaxDynamicSharedMemorySize, SMEM_BYTES);
    cudaFuncSetAttribute(kv_mma_kernel,
                         cudaFuncAttributeMaxDynamicSharedMemorySize, KV_SMEM_BYTES);
    cudaFuncSetAttribute(attn_mma_kernel,
                         cudaFuncAttributeMaxDynamicSharedMemorySize, AT_SMEM_BYTES);

    void *kvp = nullptr, *ksp = nullptr;
    cudaGetSymbolAddress(&kvp, g_kv);
    cudaGetSymbolAddress(&ksp, g_ksum);
    cudaMemsetAsync(kvp, 0, sizeof(float) * BATCH * NHEAD * DHEAD * DHEAD);
    cudaMemsetAsync(ksp, 0, sizeof(float) * BATCH * NHEAD * DHEAD);

    preconv_kernel<<<(NX4 + NWQ_U + NWO_U + 255) / 256, 256>>>(x, Wqkv, Wout);

    qkv_mma_kernel<<<dim3(NPIX / 128, O1 / 128, BATCH), 256, SMEM_BYTES>>>(cm, cs);
    kv_mma_kernel<<<dim3(4, BATCH * NHEAD), 256, KV_SMEM_BYTES>>>();
    attn_mma_kernel<<<dim3(NPIX / 256, BATCH * NHEAD), 256, AT_SMEM_BYTES>>>();
    out_mma_kernel<<<dim3(NPIX / 128, CDIM / 128, BATCH), 256, SMEM_BYTES>>>(bout, y);
}

// round 16
// speedup vs baseline: 1.4921x; 1.4921x over previous
#include <cuda_runtime.h>
#include <cuda_fp16.h>
#include <cstdint>
#include <cstddef>

#define BATCH 8
#define CDIM  256
#define NPIX  4096
#define O1    1536
#define HIDD  512
#define NHEAD 8
#define DHEAD 64

typedef unsigned int u32;

// ---------------- scratch (device globals; no allocation allowed) ----------
__device__ u32    g_qu[BATCH * NHEAD * 32 * NPIX];   // q packed pair-rows
__device__ __half g_kh[BATCH * HIDD * NPIX];         // k half [bh][64][n]
__device__ __half g_vh[BATCH * HIDD * NPIX];         // v half [bh][64][n]
__device__ u32    g_o2u[BATCH * 256 * NPIX];         // out2 packed pair-rows
__device__ float  g_kv[BATCH * NHEAD * DHEAD * DHEAD];
__device__ float  g_ksum[BATCH * NHEAD * DHEAD];
__device__ u32    g_wqh[O1 * (CDIM / 2)];            // Wqkv fp16, col pairs
__device__ u32    g_woh[CDIM * (HIDD / 2)];          // Wout fp16, permuted pairs
__device__ u32    g_xh[BATCH * (CDIM / 2) * NPIX];   // x fp16, row pairs

// ---------------- helpers ---------------------------------------------------
__device__ __forceinline__ u32 h2(float lo, float hi) {
    __half2 t = __floats2half2_rn(lo, hi);
    return *reinterpret_cast<u32*>(&t);
}
__device__ __forceinline__ float elu1f(float x) {
    return x > 0.0f ? x + 1.0f : expf(x);
}
__device__ __forceinline__ void mma_f16(float c[4], const u32 a[4], const u32 b[2]) {
    asm volatile(
        "mma.sync.aligned.m16n8k16.row.col.f32.f16.f16.f32 "
        "{%0,%1,%2,%3}, {%4,%5,%6,%7}, {%8,%9}, {%0,%1,%2,%3};"
        : "+f"(c[0]), "+f"(c[1]), "+f"(c[2]), "+f"(c[3])
        : "r"(a[0]), "r"(a[1]), "r"(a[2]), "r"(a[3]), "r"(b[0]), "r"(b[1]));
}
__device__ __forceinline__ void ldsm_x4(u32& r0, u32& r1, u32& r2, u32& r3, u32 addr) {
    asm volatile("ldmatrix.sync.aligned.m8n8.x4.shared.b16 {%0,%1,%2,%3}, [%4];"
                 : "=r"(r0), "=r"(r1), "=r"(r2), "=r"(r3) : "r"(addr));
}
__device__ __forceinline__ void ldsm_x2(u32& r0, u32& r1, u32 addr) {
    asm volatile("ldmatrix.sync.aligned.m8n8.x2.shared.b16 {%0,%1}, [%2];"
                 : "=r"(r0), "=r"(r1) : "r"(addr));
}
__device__ __forceinline__ void cp_async16(u32 dst, const void* src) {
    asm volatile("cp.async.cg.shared.global [%0], [%1], 16;" :: "r"(dst), "l"(src));
}
__device__ __forceinline__ void cp_commit() {
    asm volatile("cp.async.commit_group;");
}
template <int N> __device__ __forceinline__ void cp_wait() {
    asm volatile("cp.async.wait_group %0;" :: "n"(N));
}
__device__ __forceinline__ u32 smem_addr_of(const void* p) {
    u32 a;
    asm("{ .reg .u64 t; cvta.to.shared.u64 t, %1; cvt.u32.u64 %0, t; }"
        : "=r"(a) : "l"(p));
    return a;
}

// lane-derived ldmatrix offsets (A non-trans pattern)
struct LdsmIdx { int rowoff; int coloff; };
__device__ __forceinline__ LdsmIdx ldsm_idx(int lane) {
    LdsmIdx s;
    s.rowoff = (lane & 7) + ((lane >> 3) & 1) * 8;
    s.coloff = ((lane >> 4) & 1) * 4;
    return s;
}

// ===================== big-GEMM fp16 machinery (round-11 winner) ============
#define A_STRIDE 36
#define B_STRIDE 136
#define A_ELEMS (128 * A_STRIDE)
#define B_ELEMS (32 * B_STRIDE)
#define BUF_ELEMS (A_ELEMS + B_ELEMS)
#define BUF_BYTES (BUF_ELEMS * 4)
#define SMEM_BYTES (3 * BUF_BYTES)          // 107520

struct Frag { float c[2][8][4]; };

__device__ __forceinline__ void stage_cp(
    u32 sbase, const u32* __restrict__ A, int lda,
    const u32* __restrict__ B, int ldb, int o0, int n0, int ku0, int tid)
{
    const u32 abase = sbase;
    const u32 bbase = sbase + A_ELEMS * 4;
#pragma unroll
    for (int i = 0; i < 4; ++i) {
        const int fi = tid + i * 256;
        const int row = fi >> 3, c4 = (fi & 7) * 4;
        cp_async16(abase + (u32)(row * A_STRIDE + c4) * 4,
                   &A[(size_t)(o0 + row) * lda + ku0 + c4]);
    }
#pragma unroll
    for (int i = 0; i < 4; ++i) {
        const int fi = tid + i * 256;
        const int row = fi >> 5, c4 = (fi & 31) * 4;
        cp_async16(bbase + (u32)(row * B_STRIDE + c4) * 4,
                   &B[(size_t)(ku0 + row) * ldb + n0 + c4]);
    }
    cp_commit();
}

__device__ __forceinline__ void chunk_mma(
    Frag& fr, const u32* sm_u, u32 abase_u32,
    int warp_m, int warp_n, int lq, int kq, const LdsmIdx& si)
{
    const u32* Bs = sm_u + A_ELEMS;
#pragma unroll
    for (int ks = 0; ks < 4; ++ks) {
        const int kb = ks * 8 + kq;
        u32 a[2][4];
#pragma unroll
        for (int mt = 0; mt < 2; ++mt) {
            const int row = warp_m + mt * 16 + si.rowoff;
            ldsm_x4(a[mt][0], a[mt][1], a[mt][2], a[mt][3],
                    abase_u32 + (u32)(row * A_STRIDE + ks * 8 + si.coloff) * 4);
        }
        u32 bfr[8][2];
#pragma unroll
        for (int nt = 0; nt < 8; ++nt) {
            const int n = warp_n + nt * 8 + lq;
            bfr[nt][0] = Bs[kb * B_STRIDE + n];
            bfr[nt][1] = Bs[(kb + 4) * B_STRIDE + n];
        }
#pragma unroll
        for (int mt = 0; mt < 2; ++mt)
#pragma unroll
            for (int nt = 0; nt < 8; ++nt)
                mma_f16(fr.c[mt][nt], a[mt], bfr[nt]);
    }
}

__device__ __forceinline__ void gemm_mainloop(
    Frag& fr, const u32* __restrict__ A, int lda,
    const u32* __restrict__ B, int ldb,
    int o0, int n0, int NC, u32* sm_u)
{
    const int tid = threadIdx.x;
    const int wid = tid >> 5, lane = tid & 31;
    const int warp_m = (wid & 3) * 32;
    const int warp_n = (wid >> 2) * 64;
    const int lq = lane >> 2, kq = lane & 3;
    const LdsmIdx si = ldsm_idx(lane);

    const u32 sbase = smem_addr_of(sm_u);

#pragma unroll
    for (int mt = 0; mt < 2; ++mt)
#pragma unroll
        for (int nt = 0; nt < 8; ++nt)
#pragma unroll
            for (int i = 0; i < 4; ++i) fr.c[mt][nt][i] = 0.0f;

    stage_cp(sbase, A, lda, B, ldb, o0, n0, 0, tid);
    stage_cp(sbase + BUF_BYTES, A, lda, B, ldb, o0, n0, 32, tid);

    for (int c = 0; c < NC; ++c) {
        if (c < NC - 1) cp_wait<1>(); else cp_wait<0>();
        __syncthreads();
        if (c + 2 < NC)
            stage_cp(sbase + (u32)((c + 2) % 3) * BUF_BYTES,
                     A, lda, B, ldb, o0, n0, (c + 2) * 32, tid);
        const int cur = c % 3;
        chunk_mma(fr, sm_u + (size_t)cur * BUF_ELEMS,
                  sbase + (u32)cur * BUF_BYTES, warp_m, warp_n, lq, kq, si);
    }
}

// ============================================================================
// Kernel 0a: pack weights to fp16.
// ============================================================================
#define NWQ_U (O1 * (CDIM / 2))
#define NWO_U (CDIM * (HIDD / 2))

__global__ __launch_bounds__(256) void preconv_w_kernel(
    const float* __restrict__ wq, const float* __restrict__ wo)
{
    const int i = blockIdx.x * 256 + threadIdx.x;
    if (i < NWQ_U) {
        const int o = i >> 7, j = i & 127;
        const float* p = &wq[(size_t)o * CDIM + 2 * j];
        g_wqh[i] = h2(p[0], p[1]);
    } else if (i < NWQ_U + NWO_U) {
        const int i2 = i - NWQ_U;
        const int o = i2 >> 8, jg = i2 & 255;
        const int h = jg >> 5, r = jg & 31;
        const int p0 = h * 64 + ((r >> 3) << 4) + (r & 7);
        g_woh[i2] = h2(wo[(size_t)o * HIDD + p0], wo[(size_t)o * HIDD + p0 + 8]);
    }
}

// ============================================================================
// Kernel 0b: pack x to fp16 row pairs.
// ============================================================================
__global__ __launch_bounds__(256) void preconv_x_kernel(const float* __restrict__ x)
{
    const int i = blockIdx.x * 256 + threadIdx.x;
    const int n4 = (i & 1023) * 4;
    const int j  = (i >> 10) & 127;
    const int b  = i >> 17;
    const float* r0 = &x[((size_t)b * CDIM + 2 * j) * NPIX + n4];
    const float* r1 = r0 + NPIX;
    float4 a = *reinterpret_cast<const float4*>(r0);
    float4 c = *reinterpret_cast<const float4*>(r1);
    uint4 w;
    w.x = h2(a.x, c.x); w.y = h2(a.y, c.y);
    w.z = h2(a.z, c.z); w.w = h2(a.w, c.w);
    *reinterpret_cast<uint4*>(&g_xh[(((size_t)b * 128 + j) * NPIX + n4)]) = w;
}

// ============================================================================
// Kernel 1: qkv GEMM (fp16). Epilogue: q -> packed pair-rows, k/v -> half.
// ============================================================================
__global__ __launch_bounds__(256, 2) void qkv_mma_kernel(
    const float* __restrict__ cm, const float* __restrict__ csp)
{
    extern __shared__ u32 sm_u[];
    const int b  = blockIdx.z;
    const int o0 = blockIdx.y * 128;
    const int n0 = blockIdx.x * 128;

    Frag fr;
    gemm_mainloop(fr, g_wqh, CDIM / 2, g_xh + (size_t)b * 128 * NPIX, NPIX,
                  o0, n0, 4, sm_u);

    const int tid = threadIdx.x;
    const int wid = tid >> 5, lane = tid & 31;
    const int warp_m = (wid & 3) * 32;
    const int warp_n = (wid >> 2) * 64;
    const int lq = lane >> 2, kq = lane & 3;

    const int sec = o0 >> 9;
    const int obase = o0 & 511;
    const float cs = (sec == 1) ? *csp : 0.0f;
    const float* cmb = cm + (size_t)b * NPIX;

#pragma unroll
    for (int nt = 0; nt < 8; ++nt) {
        const int cg = n0 + warp_n + nt * 8 + kq * 2;
        float m0 = 1.0f, m1 = 1.0f;
        if (sec == 1) {
            m0 = 1.0f + cs * cmb[cg];
            m1 = 1.0f + cs * cmb[cg + 1];
        }
#pragma unroll
        for (int mt = 0; mt < 2; ++mt) {
            const int rl = warp_m + mt * 16 + lq;
            const int grow = obase + rl;
            float v0 = fr.c[mt][nt][0], v1 = fr.c[mt][nt][1];
            float v2 = fr.c[mt][nt][2], v3 = fr.c[mt][nt][3];
            if (sec == 0) {
                v0 = elu1f(v0); v1 = elu1f(v1); v2 = elu1f(v2); v3 = elu1f(v3);
                const int h = grow >> 6, wh = grow & 63;
                const int j = ((wh >> 4) << 3) | (wh & 7);
                const size_t urow = (size_t)(b * NHEAD + h) * 32 + j;
                uint2 w;
                w.x = h2(v0, v2);
                w.y = h2(v1, v3);
                *reinterpret_cast<uint2*>(&g_qu[urow * NPIX + cg]) = w;
            } else {
                __half* dst = (sec == 1) ? g_kh : g_vh;
                if (sec == 1) {
                    v0 = elu1f(v0) * m0; v1 = elu1f(v1) * m1;
                    v2 = elu1f(v2) * m0; v3 = elu1f(v3) * m1;
                }
                *reinterpret_cast<u32*>(
                    &dst[((size_t)b * HIDD + grow) * NPIX + cg]) = h2(v0, v1);
                *reinterpret_cast<u32*>(
                    &dst[((size_t)b * HIDD + grow + 8) * NPIX + cg]) = h2(v2, v3);
            }
        }
    }
}

// ============================================================================
// Kernel 4: y = Wout @ out2 + bout
// ============================================================================
__global__ __launch_bounds__(256, 2) void out_mma_kernel(
    const float* __restrict__ bout, float* __restrict__ y)
{
    extern __shared__ u32 sm_u[];
    const int b  = blockIdx.z;
    const int o0 = blockIdx.y * 128;
    const int n0 = blockIdx.x * 128;

    Frag fr;
    gemm_mainloop(fr, g_woh, HIDD / 2, g_o2u + (size_t)b * 256 * NPIX, NPIX,
                  o0, n0, 8, sm_u);

    const int tid = threadIdx.x;
    const int wid = tid >> 5, lane = tid & 31;
    const int warp_m = (wid & 3) * 32;
    const int warp_n = (wid >> 2) * 64;
    const int lq = lane >> 2, kq = lane & 3;

#pragma unroll
    for (int mt = 0; mt < 2; ++mt) {
        const int rl = warp_m + mt * 16 + lq;
#pragma unroll
        for (int ri = 0; ri < 2; ++ri) {
            const int grow = o0 + rl + ri * 8;
            const float bo = bout[grow];
#pragma unroll
            for (int nt = 0; nt < 8; ++nt) {
                const int cg = n0 + warp_n + nt * 8 + kq * 2;
                float2 w;
                w.x = fr.c[mt][nt][2 * ri + 0] + bo;
                w.y = fr.c[mt][nt][2 * ri + 1] + bo;
                *reinterpret_cast<float2*>(
                    &y[((size_t)b * CDIM + grow) * NPIX + cg]) = w;
            }
        }
    }
}

// ============================================================================
// Kernel 2 (fp16 MMA, fully async): A = k [64 d][np], B = v [80 e][np]
// (v rows 0-63 via cp.async; row 64 = ones, rows 65-79 = 0, static).
// out[d][e<64] -> kv (atomic), out[d][64] -> ksum (atomic).
// Grid (4 splits, 64 bh); 8 chunks of 64 np (128 n), 2 buffers.
// ============================================================================
#define KV_ASTR 68
#define KV_BSTR 68
#define KV_AE (64 * KV_ASTR)
#define KV_BE (80 * KV_BSTR)
#define KV_SMEM_BYTES ((2 * KV_AE + 2 * KV_BE) * 4)   // 78336

__global__ __launch_bounds__(256) void kv_mma_kernel()
{
    extern __shared__ u32 sm_u[];
    u32* As = sm_u;
    u32* Bs = sm_u + 2 * KV_AE;
    const u32 a_sbase = smem_addr_of(As);
    const u32 b_sbase = smem_addr_of(Bs);

    const int bh    = blockIdx.y;
    const int split = blockIdx.x;
    const int tid = threadIdx.x;
    const int wid = tid >> 5, lane = tid & 31;
    const int warp_m = (wid & 3) * 16;
    const int warp_n = (wid >> 2) * 40;
    const int lq = lane >> 2, kq = lane & 3;
    const LdsmIdx si = ldsm_idx(lane);

    const int b_row = (lane & 7) + ((lane >> 4) & 1) * 8;
    const int b_col = ((lane >> 3) & 1) * 4;
    const int l2 = lane & 15;
    const int b2_row = l2 & 7;
    const int b2_col = ((l2 >> 3) & 1) * 4;

    const u32* kbase = reinterpret_cast<const u32*>(g_kh)
                       + (size_t)bh * 64 * 2048 + split * 512;
    const u32* vbase = reinterpret_cast<const u32*>(g_vh)
                       + (size_t)bh * 64 * 2048 + split * 512;

    for (int f = tid; f < 16 * 64 * 2; f += 256) {
        const int buf = f >> 10;
        const int r = 64 + ((f >> 6) & 15), c = f & 63;
        Bs[buf * KV_BE + r * KV_BSTR + c] = (r == 64) ? 0x3C003C00u : 0u;
    }

    auto stage = [&](int cu0, int buf) {
#pragma unroll
        for (int i = 0; i < 4; ++i) {
            const int f = tid + i * 256;
            const int d = f >> 4, c4 = (f & 15) * 4;
            cp_async16(a_sbase + (u32)(buf * KV_AE + d * KV_ASTR + c4) * 4,
                       &kbase[(size_t)d * 2048 + cu0 + c4]);
        }
#pragma unroll
        for (int i = 0; i < 4; ++i) {
            const int f = tid + i * 256;
            const int e = f >> 4, c4 = (f & 15) * 4;
            cp_async16(b_sbase + (u32)(buf * KV_BE + e * KV_BSTR + c4) * 4,
                       &vbase[(size_t)e * 2048 + cu0 + c4]);
        }
        cp_commit();
    };

    float fr[5][4];
#pragma unroll
    for (int nt = 0; nt < 5; ++nt)
#pragma unroll
        for (int i = 0; i < 4; ++i) fr[nt][i] = 0.0f;

    stage(0, 0);
    stage(64, 1);

    for (int c = 0; c < 8; ++c) {
        if (c < 7) cp_wait<1>(); else cp_wait<0>();
        __syncthreads();

        const int cur = c & 1;
        const u32 ab = a_sbase + (u32)(cur * KV_AE) * 4;
        const u32 bb = b_sbase + (u32)(cur * KV_BE) * 4;
#pragma unroll
        for (int ks = 0; ks < 8; ++ks) {
            u32 a[4];
            ldsm_x4(a[0], a[1], a[2], a[3],
                    ab + (u32)((warp_m + si.rowoff) * KV_ASTR + ks * 8 + si.coloff) * 4);
            u32 bfr[5][2];
            ldsm_x4(bfr[0][0], bfr[0][1], bfr[1][0], bfr[1][1],
                    bb + (u32)((warp_n + b_row) * KV_BSTR + ks * 8 + b_col) * 4);
            ldsm_x4(bfr[2][0], bfr[2][1], bfr[3][0], bfr[3][1],
                    bb + (u32)((warp_n + 16 + b_row) * KV_BSTR + ks * 8 + b_col) * 4);
            ldsm_x2(bfr[4][0], bfr[4][1],
                    bb + (u32)((warp_n + 32 + b2_row) * KV_BSTR + ks * 8 + b2_col) * 4);
#pragma unroll
            for (int nt = 0; nt < 5; ++nt)
                mma_f16(fr[nt], a, bfr[nt]);
        }

        if (c < 6) {
            __syncthreads();
            stage((c + 2) * 64, cur);
        }
    }

    float* kvout = g_kv + (size_t)bh * DHEAD * DHEAD;
    float* ksout = g_ksum + (size_t)bh * DHEAD;
#pragma unroll
    for (int nt = 0; nt < 5; ++nt) {
#pragma unroll
        for (int i = 0; i < 4; ++i) {
            const int e = warp_n + nt * 8 + kq * 2 + (i & 1);
            const int d = warp_m + lq + (i >> 1) * 8;
            if (e < 64)       atomicAdd(&kvout[d * DHEAD + e], fr[nt][i]);
            else if (e == 64) atomicAdd(&ksout[d], fr[nt][i]);
        }
    }
}

// ============================================================================
// Kernel 3 (fp16 MMA): A = [kv^T pairs ; ksum row 64 ; 0 pad], B = q packed.
// ============================================================================
#define AT_ASTR 36
#define AT_AE (80 * AT_ASTR)
#define AT_BSTR 264
#define AT_BE (32 * AT_BSTR)
#define AT_SMEM_BYTES ((AT_AE + AT_BE) * 4)

__global__ __launch_bounds__(256, 2) void attn_mma_kernel()
{
    extern __shared__ u32 sm_u[];
    u32* As = sm_u;
    u32* Bs = sm_u + AT_AE;
    const u32 a_sbase = smem_addr_of(As);
    const u32 b_sbase = smem_addr_of(Bs);

    const int bh = blockIdx.y;
    const int n0 = blockIdx.x * 256;
    const int tid = threadIdx.x;
    const int wid = tid >> 5, lane = tid & 31;
    const int warp_n = wid * 32;
    const int lq = lane >> 2, kq = lane & 3;
    const LdsmIdx si = ldsm_idx(lane);

    const u32*   qbase  = g_qu + (size_t)bh * 32 * NPIX;
    const float* kvbase = g_kv + (size_t)bh * DHEAD * DHEAD;

#pragma unroll
    for (int i = 0; i < 8; ++i) {
        const int f = tid + i * 256;
        const int d = f >> 6, c4 = (f & 63) * 4;
        cp_async16(b_sbase + (u32)(d * AT_BSTR + c4) * 4,
                   &qbase[(size_t)d * NPIX + n0 + c4]);
    }
    cp_commit();

    for (int f = tid; f < 15 * AT_ASTR; f += 256) As[65 * AT_ASTR + f] = 0u;
    if (tid < 32) {
        const int j = tid;
        const int p0 = ((j >> 3) << 4) | (j & 7);
        As[64 * AT_ASTR + j] = h2(g_ksum[bh * DHEAD + p0],
                                  g_ksum[bh * DHEAD + p0 + 8]);
    }
    for (int f = tid; f < 64 * 32; f += 256) {
        const int e = f >> 5, j = f & 31;
        const int p0 = ((j >> 3) << 4) | (j & 7);
        As[e * AT_ASTR + j] = h2(kvbase[p0 * DHEAD + e],
                                 kvbase[(p0 + 8) * DHEAD + e]);
    }
    cp_wait<0>();
    __syncthreads();

    float fr[5][4][4];
#pragma unroll
    for (int mt = 0; mt < 5; ++mt)
#pragma unroll
        for (int nt = 0; nt < 4; ++nt)
#pragma unroll
            for (int i = 0; i < 4; ++i) fr[mt][nt][i] = 0.0f;

#pragma unroll
    for (int ks = 0; ks < 4; ++ks) {
        const int kb = ks * 8 + kq;
        u32 a[5][4];
#pragma unroll
        for (int mt = 0; mt < 5; ++mt) {
            const int row = mt * 16 + si.rowoff;
            ldsm_x4(a[mt][0], a[mt][1], a[mt][2], a[mt][3],
                    a_sbase + (u32)(row * AT_ASTR + ks * 8 + si.coloff) * 4);
        }
        u32 bfr[4][2];
#pragma unroll
        for (int nt = 0; nt < 4; ++nt) {
            const int n = warp_n + nt * 8 + lq;
            bfr[nt][0] = Bs[kb * AT_BSTR + n];
            bfr[nt][1] = Bs[(kb + 4) * AT_BSTR + n];
        }
#pragma unroll
        for (int mt = 0; mt < 5; ++mt)
#pragma unroll
            for (int nt = 0; nt < 4; ++nt)
                mma_f16(fr[mt][nt], a[mt], bfr[nt]);
    }

    u32* obase = g_o2u + (size_t)bh * 32 * NPIX;
#pragma unroll
    for (int nt = 0; nt < 4; ++nt) {
        const float den0 = __shfl_sync(0xffffffffu, fr[4][nt][0], kq);
        const float den1 = __shfl_sync(0xffffffffu, fr[4][nt][1], kq);
        const float z0 = 1.0f / (den0 + 1e-6f);
        const float z1 = 1.0f / (den1 + 1e-6f);
        const int cg = n0 + warp_n + nt * 8 + kq * 2;
#pragma unroll
        for (int mt = 0; mt < 4; ++mt) {
            const int j = mt * 8 + lq;
            uint2 w;
            w.x = h2(fr[mt][nt][0] * z0, fr[mt][nt][2] * z0);
            w.y = h2(fr[mt][nt][1] * z1, fr[mt][nt][3] * z1);
            *reinterpret_cast<uint2*>(&obase[(size_t)j * NPIX + cg]) = w;
        }
    }
}

// ============================================================================
extern "C" void kernel_launch(void* const* d_in, const int* in_sizes, int n_in,
                              void* d_out, int out_size)
{
    const float* x    = (const float*)d_in[0];
    const float* cm   = (const float*)d_in[1];
    const float* Wqkv = (const float*)d_in[2];
    const float* Wout = (const float*)d_in[3];
    const float* bout = (const float*)d_in[4];
    const float* cs   = (const float*)d_in[5];
    float* y = (float*)d_out;

    cudaFuncSetAttribute(qkv_mma_kernel,
                         cudaFuncAttributeMaxDynamicSharedMemorySize, SMEM_BYTES);
    cudaFuncSetAttribute(out_mma_kernel,
                         cudaFuncAttributeMaxDynamicSharedMemorySize, SMEM_BYTES);
    cudaFuncSetAttribute(kv_mma_kernel,
                         cudaFuncAttributeMaxDynamicSharedMemorySize, KV_SMEM_BYTES);
    cudaFuncSetAttribute(attn_mma_kernel,
                         cudaFuncAttributeMaxDynamicSharedMemorySize, AT_SMEM_BYTES);

    void *kvp = nullptr, *ksp = nullptr;
    cudaGetSymbolAddress(&kvp, g_kv);
    cudaGetSymbolAddress(&ksp, g_ksum);
    cudaMemsetAsync(kvp, 0, sizeof(float) * BATCH * NHEAD * DHEAD * DHEAD);
    cudaMemsetAsync(ksp, 0, sizeof(float) * BATCH * NHEAD * DHEAD);

    preconv_w_kernel<<<(NWQ_U + NWO_U + 255) / 256, 256>>>(Wqkv, Wout);
    preconv_x_kernel<<<(BATCH * 128 * NPIX / 4) / 256, 256>>>(x);

    qkv_mma_kernel<<<dim3(NPIX / 128, O1 / 128, BATCH), 256, SMEM_BYTES>>>(cm, cs);
    kv_mma_kernel<<<dim3(4, BATCH * NHEAD), 256, KV_SMEM_BYTES>>>();
    attn_mma_kernel<<<dim3(NPIX / 256, BATCH * NHEAD), 256, AT_SMEM_BYTES>>>();
    out_mma_kernel<<<dim3(NPIX / 128, CDIM / 128, BATCH), 256, SMEM_BYTES>>>(bout, y);
}

// round 17
// speedup vs baseline: 1.5026x; 1.0070x over previous
#include <cuda_runtime.h>
#include <cuda_fp16.h>
#include <cstdint>
#include <cstddef>

#define BATCH 8
#define CDIM  256
#define NPIX  4096
#define O1    1536
#define HIDD  512
#define NHEAD 8
#define DHEAD 64

typedef unsigned int u32;

// ---------------- scratch (device globals; no allocation allowed) ----------
__device__ u32    g_qu[BATCH * NHEAD * 32 * NPIX];   // q packed pair-rows
__device__ __half g_kh[BATCH * HIDD * NPIX];         // k half [bh][64][n]
__device__ __half g_vh[BATCH * HIDD * NPIX];         // v half [bh][64][n]
__device__ u32    g_o2u[BATCH * 256 * NPIX];         // out2 packed pair-rows
__device__ float  g_kv[BATCH * NHEAD * DHEAD * DHEAD];
__device__ float  g_ksum[BATCH * NHEAD * DHEAD];
__device__ u32    g_wqh[O1 * (CDIM / 2)];            // Wqkv fp16, col pairs
__device__ u32    g_woh[CDIM * (HIDD / 2)];          // Wout fp16, permuted pairs
__device__ u32    g_xh[BATCH * (CDIM / 2) * NPIX];   // x fp16, row pairs

// ---------------- helpers ---------------------------------------------------
__device__ __forceinline__ u32 h2(float lo, float hi) {
    __half2 t = __floats2half2_rn(lo, hi);
    return *reinterpret_cast<u32*>(&t);
}
__device__ __forceinline__ float elu1f(float x) {
    return x > 0.0f ? x + 1.0f : expf(x);
}
__device__ __forceinline__ void mma_f16(float c[4], const u32 a[4], const u32 b[2]) {
    asm volatile(
        "mma.sync.aligned.m16n8k16.row.col.f32.f16.f16.f32 "
        "{%0,%1,%2,%3}, {%4,%5,%6,%7}, {%8,%9}, {%0,%1,%2,%3};"
        : "+f"(c[0]), "+f"(c[1]), "+f"(c[2]), "+f"(c[3])
        : "r"(a[0]), "r"(a[1]), "r"(a[2]), "r"(a[3]), "r"(b[0]), "r"(b[1]));
}
__device__ __forceinline__ void ldsm_x4(u32& r0, u32& r1, u32& r2, u32& r3, u32 addr) {
    asm volatile("ldmatrix.sync.aligned.m8n8.x4.shared.b16 {%0,%1,%2,%3}, [%4];"
                 : "=r"(r0), "=r"(r1), "=r"(r2), "=r"(r3) : "r"(addr));
}
__device__ __forceinline__ void ldsm_x2(u32& r0, u32& r1, u32 addr) {
    asm volatile("ldmatrix.sync.aligned.m8n8.x2.shared.b16 {%0,%1}, [%2];"
                 : "=r"(r0), "=r"(r1) : "r"(addr));
}
__device__ __forceinline__ void cp_async16(u32 dst, const void* src) {
    asm volatile("cp.async.cg.shared.global [%0], [%1], 16;" :: "r"(dst), "l"(src));
}
__device__ __forceinline__ void cp_commit() {
    asm volatile("cp.async.commit_group;");
}
template <int N> __device__ __forceinline__ void cp_wait() {
    asm volatile("cp.async.wait_group %0;" :: "n"(N));
}
__device__ __forceinline__ u32 smem_addr_of(const void* p) {
    u32 a;
    asm("{ .reg .u64 t; cvta.to.shared.u64 t, %1; cvt.u32.u64 %0, t; }"
        : "=r"(a) : "l"(p));
    return a;
}

// lane-derived ldmatrix offsets (A non-trans pattern)
struct LdsmIdx { int rowoff; int coloff; };
__device__ __forceinline__ LdsmIdx ldsm_idx(int lane) {
    LdsmIdx s;
    s.rowoff = (lane & 7) + ((lane >> 3) & 1) * 8;
    s.coloff = ((lane >> 4) & 1) * 4;
    return s;
}

// ===================== big-GEMM fp16 machinery (round-11 winner) ============
#define A_STRIDE 36
#define B_STRIDE 136
#define A_ELEMS (128 * A_STRIDE)
#define B_ELEMS (32 * B_STRIDE)
#define BUF_ELEMS (A_ELEMS + B_ELEMS)
#define BUF_BYTES (BUF_ELEMS * 4)
#define SMEM_BYTES (3 * BUF_BYTES)          // 107520

struct Frag { float c[2][8][4]; };

__device__ __forceinline__ void stage_cp(
    u32 sbase, const u32* __restrict__ A, int lda,
    const u32* __restrict__ B, int ldb, int o0, int n0, int ku0, int tid)
{
    const u32 abase = sbase;
    const u32 bbase = sbase + A_ELEMS * 4;
#pragma unroll
    for (int i = 0; i < 4; ++i) {
        const int fi = tid + i * 256;
        const int row = fi >> 3, c4 = (fi & 7) * 4;
        cp_async16(abase + (u32)(row * A_STRIDE + c4) * 4,
                   &A[(size_t)(o0 + row) * lda + ku0 + c4]);
    }
#pragma unroll
    for (int i = 0; i < 4; ++i) {
        const int fi = tid + i * 256;
        const int row = fi >> 5, c4 = (fi & 31) * 4;
        cp_async16(bbase + (u32)(row * B_STRIDE + c4) * 4,
                   &B[(size_t)(ku0 + row) * ldb + n0 + c4]);
    }
    cp_commit();
}

__device__ __forceinline__ void chunk_mma(
    Frag& fr, const u32* sm_u, u32 abase_u32,
    int warp_m, int warp_n, int lq, int kq, const LdsmIdx& si)
{
    const u32* Bs = sm_u + A_ELEMS;
#pragma unroll
    for (int ks = 0; ks < 4; ++ks) {
        const int kb = ks * 8 + kq;
        u32 a[2][4];
#pragma unroll
        for (int mt = 0; mt < 2; ++mt) {
            const int row = warp_m + mt * 16 + si.rowoff;
            ldsm_x4(a[mt][0], a[mt][1], a[mt][2], a[mt][3],
                    abase_u32 + (u32)(row * A_STRIDE + ks * 8 + si.coloff) * 4);
        }
        u32 bfr[8][2];
#pragma unroll
        for (int nt = 0; nt < 8; ++nt) {
            const int n = warp_n + nt * 8 + lq;
            bfr[nt][0] = Bs[kb * B_STRIDE + n];
            bfr[nt][1] = Bs[(kb + 4) * B_STRIDE + n];
        }
#pragma unroll
        for (int mt = 0; mt < 2; ++mt)
#pragma unroll
            for (int nt = 0; nt < 8; ++nt)
                mma_f16(fr.c[mt][nt], a[mt], bfr[nt]);
    }
}

__device__ __forceinline__ void gemm_mainloop(
    Frag& fr, const u32* __restrict__ A, int lda,
    const u32* __restrict__ B, int ldb,
    int o0, int n0, int NC, u32* sm_u)
{
    const int tid = threadIdx.x;
    const int wid = tid >> 5, lane = tid & 31;
    const int warp_m = (wid & 3) * 32;
    const int warp_n = (wid >> 2) * 64;
    const int lq = lane >> 2, kq = lane & 3;
    const LdsmIdx si = ldsm_idx(lane);

    const u32 sbase = smem_addr_of(sm_u);

#pragma unroll
    for (int mt = 0; mt < 2; ++mt)
#pragma unroll
        for (int nt = 0; nt < 8; ++nt)
#pragma unroll
            for (int i = 0; i < 4; ++i) fr.c[mt][nt][i] = 0.0f;

    stage_cp(sbase, A, lda, B, ldb, o0, n0, 0, tid);
    stage_cp(sbase + BUF_BYTES, A, lda, B, ldb, o0, n0, 32, tid);

    for (int c = 0; c < NC; ++c) {
        if (c < NC - 1) cp_wait<1>(); else cp_wait<0>();
        __syncthreads();
        if (c + 2 < NC)
            stage_cp(sbase + (u32)((c + 2) % 3) * BUF_BYTES,
                     A, lda, B, ldb, o0, n0, (c + 2) * 32, tid);
        const int cur = c % 3;
        chunk_mma(fr, sm_u + (size_t)cur * BUF_ELEMS,
                  sbase + (u32)cur * BUF_BYTES, warp_m, warp_n, lq, kq, si);
    }
}

// ============================================================================
// Kernel 0a: pack weights to fp16 + zero g_kv/g_ksum (replaces memsets).
// ============================================================================
#define NWQ_U (O1 * (CDIM / 2))
#define NWO_U (CDIM * (HIDD / 2))
#define NZ4   ((BATCH * NHEAD * DHEAD * DHEAD + BATCH * NHEAD * DHEAD) / 4)

__global__ __launch_bounds__(256) void preconv_w_kernel(
    const float* __restrict__ wq, const float* __restrict__ wo)
{
    const int i = blockIdx.x * 256 + threadIdx.x;
    if (i < NWQ_U) {
        const int o = i >> 7, j = i & 127;
        const float* p = &wq[(size_t)o * CDIM + 2 * j];
        g_wqh[i] = h2(p[0], p[1]);
    } else if (i < NWQ_U + NWO_U) {
        const int i2 = i - NWQ_U;
        const int o = i2 >> 8, jg = i2 & 255;
        const int h = jg >> 5, r = jg & 31;
        const int p0 = h * 64 + ((r >> 3) << 4) + (r & 7);
        g_woh[i2] = h2(wo[(size_t)o * HIDD + p0], wo[(size_t)o * HIDD + p0 + 8]);
    } else if (i < NWQ_U + NWO_U + NZ4) {
        const int i3 = i - NWQ_U - NWO_U;
        const int kvq = BATCH * NHEAD * DHEAD * DHEAD / 4;
        float4 z; z.x = 0.0f; z.y = 0.0f; z.z = 0.0f; z.w = 0.0f;
        if (i3 < kvq) reinterpret_cast<float4*>(g_kv)[i3] = z;
        else          reinterpret_cast<float4*>(g_ksum)[i3 - kvq] = z;
    }
}

// ============================================================================
// Kernel 0b: pack x to fp16 row pairs.
// ============================================================================
__global__ __launch_bounds__(256) void preconv_x_kernel(const float* __restrict__ x)
{
    const int i = blockIdx.x * 256 + threadIdx.x;
    const int n4 = (i & 1023) * 4;
    const int j  = (i >> 10) & 127;
    const int b  = i >> 17;
    const float* r0 = &x[((size_t)b * CDIM + 2 * j) * NPIX + n4];
    const float* r1 = r0 + NPIX;
    float4 a = *reinterpret_cast<const float4*>(r0);
    float4 c = *reinterpret_cast<const float4*>(r1);
    uint4 w;
    w.x = h2(a.x, c.x); w.y = h2(a.y, c.y);
    w.z = h2(a.z, c.z); w.w = h2(a.w, c.w);
    *reinterpret_cast<uint4*>(&g_xh[(((size_t)b * 128 + j) * NPIX + n4)]) = w;
}

// ============================================================================
// Kernel 1: qkv GEMM (fp16). Epilogue: q -> packed pair-rows, k/v -> half.
// ============================================================================
__global__ __launch_bounds__(256, 2) void qkv_mma_kernel(
    const float* __restrict__ cm, const float* __restrict__ csp)
{
    extern __shared__ u32 sm_u[];
    const int b  = blockIdx.z;
    const int o0 = blockIdx.y * 128;
    const int n0 = blockIdx.x * 128;

    Frag fr;
    gemm_mainloop(fr, g_wqh, CDIM / 2, g_xh + (size_t)b * 128 * NPIX, NPIX,
                  o0, n0, 4, sm_u);

    const int tid = threadIdx.x;
    const int wid = tid >> 5, lane = tid & 31;
    const int warp_m = (wid & 3) * 32;
    const int warp_n = (wid >> 2) * 64;
    const int lq = lane >> 2, kq = lane & 3;

    const int sec = o0 >> 9;
    const int obase = o0 & 511;
    const float cs = (sec == 1) ? *csp : 0.0f;
    const float* cmb = cm + (size_t)b * NPIX;

#pragma unroll
    for (int nt = 0; nt < 8; ++nt) {
        const int cg = n0 + warp_n + nt * 8 + kq * 2;
        float m0 = 1.0f, m1 = 1.0f;
        if (sec == 1) {
            m0 = 1.0f + cs * cmb[cg];
            m1 = 1.0f + cs * cmb[cg + 1];
        }
#pragma unroll
        for (int mt = 0; mt < 2; ++mt) {
            const int rl = warp_m + mt * 16 + lq;
            const int grow = obase + rl;
            float v0 = fr.c[mt][nt][0], v1 = fr.c[mt][nt][1];
            float v2 = fr.c[mt][nt][2], v3 = fr.c[mt][nt][3];
            if (sec == 0) {
                v0 = elu1f(v0); v1 = elu1f(v1); v2 = elu1f(v2); v3 = elu1f(v3);
                const int h = grow >> 6, wh = grow & 63;
                const int j = ((wh >> 4) << 3) | (wh & 7);
                const size_t urow = (size_t)(b * NHEAD + h) * 32 + j;
                uint2 w;
                w.x = h2(v0, v2);
                w.y = h2(v1, v3);
                *reinterpret_cast<uint2*>(&g_qu[urow * NPIX + cg]) = w;
            } else {
                __half* dst = (sec == 1) ? g_kh : g_vh;
                if (sec == 1) {
                    v0 = elu1f(v0) * m0; v1 = elu1f(v1) * m1;
                    v2 = elu1f(v2) * m0; v3 = elu1f(v3) * m1;
                }
                *reinterpret_cast<u32*>(
                    &dst[((size_t)b * HIDD + grow) * NPIX + cg]) = h2(v0, v1);
                *reinterpret_cast<u32*>(
                    &dst[((size_t)b * HIDD + grow + 8) * NPIX + cg]) = h2(v2, v3);
            }
        }
    }
}

// ============================================================================
// Kernel 4: y = Wout @ out2 + bout
// ============================================================================
__global__ __launch_bounds__(256, 2) void out_mma_kernel(
    const float* __restrict__ bout, float* __restrict__ y)
{
    extern __shared__ u32 sm_u[];
    const int b  = blockIdx.z;
    const int o0 = blockIdx.y * 128;
    const int n0 = blockIdx.x * 128;

    Frag fr;
    gemm_mainloop(fr, g_woh, HIDD / 2, g_o2u + (size_t)b * 256 * NPIX, NPIX,
                  o0, n0, 8, sm_u);

    const int tid = threadIdx.x;
    const int wid = tid >> 5, lane = tid & 31;
    const int warp_m = (wid & 3) * 32;
    const int warp_n = (wid >> 2) * 64;
    const int lq = lane >> 2, kq = lane & 3;

#pragma unroll
    for (int mt = 0; mt < 2; ++mt) {
        const int rl = warp_m + mt * 16 + lq;
#pragma unroll
        for (int ri = 0; ri < 2; ++ri) {
            const int grow = o0 + rl + ri * 8;
            const float bo = bout[grow];
#pragma unroll
            for (int nt = 0; nt < 8; ++nt) {
                const int cg = n0 + warp_n + nt * 8 + kq * 2;
                float2 w;
                w.x = fr.c[mt][nt][2 * ri + 0] + bo;
                w.y = fr.c[mt][nt][2 * ri + 1] + bo;
                *reinterpret_cast<float2*>(
                    &y[((size_t)b * CDIM + grow) * NPIX + cg]) = w;
            }
        }
    }
}

// ============================================================================
// Kernel 2 (fp16 MMA, fully async): A = k [64 d][np], B = v [80 e][np]
// (v rows 0-63 via cp.async; row 64 = ones, rows 65-79 = 0, static).
// out[d][e<64] -> kv (atomic), out[d][64] -> ksum (atomic).
// Grid (4 splits, 64 bh); 8 chunks of 64 np (128 n), 2 buffers.
// ============================================================================
#define KV_ASTR 68
#define KV_BSTR 68
#define KV_AE (64 * KV_ASTR)
#define KV_BE (80 * KV_BSTR)
#define KV_SMEM_BYTES ((2 * KV_AE + 2 * KV_BE) * 4)   // 78336

__global__ __launch_bounds__(256) void kv_mma_kernel()
{
    extern __shared__ u32 sm_u[];
    u32* As = sm_u;
    u32* Bs = sm_u + 2 * KV_AE;
    const u32 a_sbase = smem_addr_of(As);
    const u32 b_sbase = smem_addr_of(Bs);

    const int bh    = blockIdx.y;
    const int split = blockIdx.x;
    const int tid = threadIdx.x;
    const int wid = tid >> 5, lane = tid & 31;
    const int warp_m = (wid & 3) * 16;
    const int warp_n = (wid >> 2) * 40;
    const int lq = lane >> 2, kq = lane & 3;
    const LdsmIdx si = ldsm_idx(lane);

    const int b_row = (lane & 7) + ((lane >> 4) & 1) * 8;
    const int b_col = ((lane >> 3) & 1) * 4;
    const int l2 = lane & 15;
    const int b2_row = l2 & 7;
    const int b2_col = ((l2 >> 3) & 1) * 4;

    const u32* kbase = reinterpret_cast<const u32*>(g_kh)
                       + (size_t)bh * 64 * 2048 + split * 512;
    const u32* vbase = reinterpret_cast<const u32*>(g_vh)
                       + (size_t)bh * 64 * 2048 + split * 512;

    for (int f = tid; f < 16 * 64 * 2; f += 256) {
        const int buf = f >> 10;
        const int r = 64 + ((f >> 6) & 15), c = f & 63;
        Bs[buf * KV_BE + r * KV_BSTR + c] = (r == 64) ? 0x3C003C00u : 0u;
    }

    auto stage = [&](int cu0, int buf) {
#pragma unroll
        for (int i = 0; i < 4; ++i) {
            const int f = tid + i * 256;
            const int d = f >> 4, c4 = (f & 15) * 4;
            cp_async16(a_sbase + (u32)(buf * KV_AE + d * KV_ASTR + c4) * 4,
                       &kbase[(size_t)d * 2048 + cu0 + c4]);
        }
#pragma unroll
        for (int i = 0; i < 4; ++i) {
            const int f = tid + i * 256;
            const int e = f >> 4, c4 = (f & 15) * 4;
            cp_async16(b_sbase + (u32)(buf * KV_BE + e * KV_BSTR + c4) * 4,
                       &vbase[(size_t)e * 2048 + cu0 + c4]);
        }
        cp_commit();
    };

    float fr[5][4];
#pragma unroll
    for (int nt = 0; nt < 5; ++nt)
#pragma unroll
        for (int i = 0; i < 4; ++i) fr[nt][i] = 0.0f;

    stage(0, 0);
    stage(64, 1);

    for (int c = 0; c < 8; ++c) {
        if (c < 7) cp_wait<1>(); else cp_wait<0>();
        __syncthreads();

        const int cur = c & 1;
        const u32 ab = a_sbase + (u32)(cur * KV_AE) * 4;
        const u32 bb = b_sbase + (u32)(cur * KV_BE) * 4;
#pragma unroll
        for (int ks = 0; ks < 8; ++ks) {
            u32 a[4];
            ldsm_x4(a[0], a[1], a[2], a[3],
                    ab + (u32)((warp_m + si.rowoff) * KV_ASTR + ks * 8 + si.coloff) * 4);
            u32 bfr[5][2];
            ldsm_x4(bfr[0][0], bfr[0][1], bfr[1][0], bfr[1][1],
                    bb + (u32)((warp_n + b_row) * KV_BSTR + ks * 8 + b_col) * 4);
            ldsm_x4(bfr[2][0], bfr[2][1], bfr[3][0], bfr[3][1],
                    bb + (u32)((warp_n + 16 + b_row) * KV_BSTR + ks * 8 + b_col) * 4);
            ldsm_x2(bfr[4][0], bfr[4][1],
                    bb + (u32)((warp_n + 32 + b2_row) * KV_BSTR + ks * 8 + b2_col) * 4);
#pragma unroll
            for (int nt = 0; nt < 5; ++nt)
                mma_f16(fr[nt], a, bfr[nt]);
        }

        if (c < 6) {
            __syncthreads();
            stage((c + 2) * 64, cur);
        }
    }

    float* kvout = g_kv + (size_t)bh * DHEAD * DHEAD;
    float* ksout = g_ksum + (size_t)bh * DHEAD;
#pragma unroll
    for (int nt = 0; nt < 5; ++nt) {
#pragma unroll
        for (int i = 0; i < 4; ++i) {
            const int e = warp_n + nt * 8 + kq * 2 + (i & 1);
            const int d = warp_m + lq + (i >> 1) * 8;
            if (e < 64)       atomicAdd(&kvout[d * DHEAD + e], fr[nt][i]);
            else if (e == 64) atomicAdd(&ksout[d], fr[nt][i]);
        }
    }
}

// ============================================================================
// Kernel 3 (fp16 MMA): A = [kv^T pairs ; ksum row 64 ; 0 pad], B = q packed.
// ============================================================================
#define AT_ASTR 36
#define AT_AE (80 * AT_ASTR)
#define AT_BSTR 264
#define AT_BE (32 * AT_BSTR)
#define AT_SMEM_BYTES ((AT_AE + AT_BE) * 4)

__global__ __launch_bounds__(256, 2) void attn_mma_kernel()
{
    extern __shared__ u32 sm_u[];
    u32* As = sm_u;
    u32* Bs = sm_u + AT_AE;
    const u32 a_sbase = smem_addr_of(As);
    const u32 b_sbase = smem_addr_of(Bs);

    const int bh = blockIdx.y;
    const int n0 = blockIdx.x * 256;
    const int tid = threadIdx.x;
    const int wid = tid >> 5, lane = tid & 31;
    const int warp_n = wid * 32;
    const int lq = lane >> 2, kq = lane & 3;
    const LdsmIdx si = ldsm_idx(lane);

    const u32*   qbase  = g_qu + (size_t)bh * 32 * NPIX;
    const float* kvbase = g_kv + (size_t)bh * DHEAD * DHEAD;

#pragma unroll
    for (int i = 0; i < 8; ++i) {
        const int f = tid + i * 256;
        const int d = f >> 6, c4 = (f & 63) * 4;
        cp_async16(b_sbase + (u32)(d * AT_BSTR + c4) * 4,
                   &qbase[(size_t)d * NPIX + n0 + c4]);
    }
    cp_commit();

    for (int f = tid; f < 15 * AT_ASTR; f += 256) As[65 * AT_ASTR + f] = 0u;
    if (tid < 32) {
        const int j = tid;
        const int p0 = ((j >> 3) << 4) | (j & 7);
        As[64 * AT_ASTR + j] = h2(g_ksum[bh * DHEAD + p0],
                                  g_ksum[bh * DHEAD + p0 + 8]);
    }
    for (int f = tid; f < 64 * 32; f += 256) {
        const int e = f >> 5, j = f & 31;
        const int p0 = ((j >> 3) << 4) | (j & 7);
        As[e * AT_ASTR + j] = h2(kvbase[p0 * DHEAD + e],
                                 kvbase[(p0 + 8) * DHEAD + e]);
    }
    cp_wait<0>();
    __syncthreads();

    float fr[5][4][4];
#pragma unroll
    for (int mt = 0; mt < 5; ++mt)
#pragma unroll
        for (int nt = 0; nt < 4; ++nt)
#pragma unroll
            for (int i = 0; i < 4; ++i) fr[mt][nt][i] = 0.0f;

#pragma unroll
    for (int ks = 0; ks < 4; ++ks) {
        const int kb = ks * 8 + kq;
        u32 a[5][4];
#pragma unroll
        for (int mt = 0; mt < 5; ++mt) {
            const int row = mt * 16 + si.rowoff;
            ldsm_x4(a[mt][0], a[mt][1], a[mt][2], a[mt][3],
                    a_sbase + (u32)(row * AT_ASTR + ks * 8 + si.coloff) * 4);
        }
        u32 bfr[4][2];
#pragma unroll
        for (int nt = 0; nt < 4; ++nt) {
            const int n = warp_n + nt * 8 + lq;
            bfr[nt][0] = Bs[kb * AT_BSTR + n];
            bfr[nt][1] = Bs[(kb + 4) * AT_BSTR + n];
        }
#pragma unroll
        for (int mt = 0; mt < 5; ++mt)
#pragma unroll
            for (int nt = 0; nt < 4; ++nt)
                mma_f16(fr[mt][nt], a[mt], bfr[nt]);
    }

    u32* obase = g_o2u + (size_t)bh * 32 * NPIX;
#pragma unroll
    for (int nt = 0; nt < 4; ++nt) {
        const float den0 = __shfl_sync(0xffffffffu, fr[4][nt][0], kq);
        const float den1 = __shfl_sync(0xffffffffu, fr[4][nt][1], kq);
        const float z0 = 1.0f / (den0 + 1e-6f);
        const float z1 = 1.0f / (den1 + 1e-6f);
        const int cg = n0 + warp_n + nt * 8 + kq * 2;
#pragma unroll
        for (int mt = 0; mt < 4; ++mt) {
            const int j = mt * 8 + lq;
            uint2 w;
            w.x = h2(fr[mt][nt][0] * z0, fr[mt][nt][2] * z0);
            w.y = h2(fr[mt][nt][1] * z1, fr[mt][nt][3] * z1);
            *reinterpret_cast<uint2*>(&obase[(size_t)j * NPIX + cg]) = w;
        }
    }
}

// ============================================================================
extern "C" void kernel_launch(void* const* d_in, const int* in_sizes, int n_in,
                              void* d_out, int out_size)
{
    const float* x    = (const float*)d_in[0];
    const float* cm   = (const float*)d_in[1];
    const float* Wqkv = (const float*)d_in[2];
    const float* Wout = (const float*)d_in[3];
    const float* bout = (const float*)d_in[4];
    const float* cs   = (const float*)d_in[5];
    float* y = (float*)d_out;

    cudaFuncSetAttribute(qkv_mma_kernel,
                         cudaFuncAttributeMaxDynamicSharedMemorySize, SMEM_BYTES);
    cudaFuncSetAttribute(out_mma_kernel,
                         cudaFuncAttributeMaxDynamicSharedMemorySize, SMEM_BYTES);
    cudaFuncSetAttribute(kv_mma_kernel,
                         cudaFuncAttributeMaxDynamicSharedMemorySize, KV_SMEM_BYTES);
    cudaFuncSetAttribute(attn_mma_kernel,
                         cudaFuncAttributeMaxDynamicSharedMemorySize, AT_SMEM_BYTES);

    preconv_w_kernel<<<(NWQ_U + NWO_U + NZ4 + 255) / 256, 256>>>(Wqkv, Wout);
    preconv_x_kernel<<<(BATCH * 128 * NPIX / 4) / 256, 256>>>(x);

    qkv_mma_kernel<<<dim3(NPIX / 128, O1 / 128, BATCH), 256, SMEM_BYTES>>>(cm, cs);
    kv_mma_kernel<<<dim3(4, BATCH * NHEAD), 256, KV_SMEM_BYTES>>>();
    attn_mma_kernel<<<dim3(NPIX / 256, BATCH * NHEAD), 256, AT_SMEM_BYTES>>>();
    out_mma_kernel<<<dim3(NPIX / 128, CDIM / 128, BATCH), 256, SMEM_BYTES>>>(bout, y);
}